// round 1
// baseline (speedup 1.0000x reference)
#include <cuda_runtime.h>

#define NATOMS 25000
#define NPAIRS 500000

// Scratch (device globals; no allocation allowed)
__device__ __align__(16) float g_h[NATOMS * 64];
__device__ __align__(16) float g_p[NATOMS * 64];
__device__ __align__(16) float g_newp[NATOMS * 64];

// Accurate-enough fast tanh: 1 - 2/(e^{2x}+1), MUFU ex2 + approx divide (~1e-6 rel err)
__device__ __forceinline__ float tfast(float x) {
    x = fminf(fmaxf(x, -15.f), 15.f);
    float e = __expf(2.f * x);
    return 1.f - __fdividef(2.f, e + 1.f);
}

// 4-pair x 4-col register-tile GEMM step over 4 k values (float4 loads)
__device__ __forceinline__ void mm4(float acc[4][4], const float* __restrict__ A, int lda,
                                    const float* __restrict__ W, int ldw, int k4) {
    float4 w0 = *(const float4*)(W + (k4 * 4 + 0) * ldw);
    float4 w1 = *(const float4*)(W + (k4 * 4 + 1) * ldw);
    float4 w2 = *(const float4*)(W + (k4 * 4 + 2) * ldw);
    float4 w3 = *(const float4*)(W + (k4 * 4 + 3) * ldw);
#pragma unroll
    for (int i = 0; i < 4; i++) {
        float4 a = *(const float4*)(A + i * lda + k4 * 4);
        acc[i][0] = fmaf(a.x, w0.x, fmaf(a.y, w1.x, fmaf(a.z, w2.x, fmaf(a.w, w3.x, acc[i][0]))));
        acc[i][1] = fmaf(a.x, w0.y, fmaf(a.y, w1.y, fmaf(a.z, w2.y, fmaf(a.w, w3.y, acc[i][1]))));
        acc[i][2] = fmaf(a.x, w0.z, fmaf(a.y, w1.z, fmaf(a.z, w2.z, fmaf(a.w, w3.z, acc[i][2]))));
        acc[i][3] = fmaf(a.x, w0.w, fmaf(a.y, w1.w, fmaf(a.z, w2.w, fmaf(a.w, w3.w, acc[i][3]))));
    }
}

__device__ __forceinline__ void mm8(float acc[8][4], const float* __restrict__ A, int lda,
                                    const float* __restrict__ W, int ldw, int k4) {
    float4 w0 = *(const float4*)(W + (k4 * 4 + 0) * ldw);
    float4 w1 = *(const float4*)(W + (k4 * 4 + 1) * ldw);
    float4 w2 = *(const float4*)(W + (k4 * 4 + 2) * ldw);
    float4 w3 = *(const float4*)(W + (k4 * 4 + 3) * ldw);
#pragma unroll
    for (int i = 0; i < 8; i++) {
        float4 a = *(const float4*)(A + i * lda + k4 * 4);
        acc[i][0] = fmaf(a.x, w0.x, fmaf(a.y, w1.x, fmaf(a.z, w2.x, fmaf(a.w, w3.x, acc[i][0]))));
        acc[i][1] = fmaf(a.x, w0.y, fmaf(a.y, w1.y, fmaf(a.z, w2.y, fmaf(a.w, w3.y, acc[i][1]))));
        acc[i][2] = fmaf(a.x, w0.z, fmaf(a.y, w1.z, fmaf(a.z, w2.z, fmaf(a.w, w3.z, acc[i][2]))));
        acc[i][3] = fmaf(a.x, w0.w, fmaf(a.y, w1.w, fmaf(a.z, w2.w, fmaf(a.w, w3.w, acc[i][3]))));
    }
}

// ---------------------------------------------------------------------------
// Pair kernel: per-depth fused pair pipeline.
// 128 pairs per block, 256 threads, ~196KB dynamic smem.
// ---------------------------------------------------------------------------
#define PAIR_SMEM_FLOATS 50112
#define PAIR_SMEM_BYTES  (PAIR_SMEM_FLOATS * 4)

__global__ __launch_bounds__(256, 1) void pair_kernel(
    const int* __restrict__ ind2, const float* __restrict__ basis,
    const float* __restrict__ w1, const float* __restrict__ b1,    // pi_w1[d] 128x64, pi_b1[d] 64
    const float* __restrict__ w2, const float* __restrict__ b2,    // pi_w2[d] 64x256, pi_b2[d] 256
    const float* __restrict__ wi1, const float* __restrict__ wi2)  // ii_w1[d], ii_w2[d] 64x64
{
    extern __shared__ float sm[];
    float* sW2    = sm;             // 16384 (w2 64x256)
    float* sWA    = sm + 16384;     // 8192  (stage1: w1 128x64; stages 3/4: wi1@0, wi2@4096)
    float* sPIJ   = sm + 24576;     // 16384 (stage1 input; then inter=+0, t1=+8192)
    float* sWW1   = sm + 40960;     // 8192
    float* sB1    = sm + 49152;     // 64
    float* sB2    = sm + 49216;     // 256
    float* sBasis = sm + 49472;     // 512
    int*   sIdx   = (int*)(sm + 49984);  // 128

    const int tid = threadIdx.x;
    const int pairbase = blockIdx.x * 128;

    // Stage weights + pair metadata
    for (int i = tid; i < 4096; i += 256) ((float4*)sW2)[i] = ((const float4*)w2)[i];
    for (int i = tid; i < 2048; i += 256) ((float4*)sWA)[i] = ((const float4*)w1)[i];
    if (tid < 64) sB1[tid] = b1[tid];
    if (tid < 128) {
        sB2[tid] = b2[tid];
        sB2[tid + 128] = b2[tid + 128];
        int p = pairbase + tid;
        if (p < NPAIRS) {
            sIdx[tid] = ind2[2 * p];
            ((float4*)sBasis)[tid] = ((const float4*)basis)[p];
        } else {
            sIdx[tid] = -1;
            ((float4*)sBasis)[tid] = make_float4(0.f, 0.f, 0.f, 0.f);
        }
    }
    // Gather pij = [h[i] | h[j]] for 128 pairs (128 floats each = 32 float4)
#pragma unroll
    for (int r = 0; r < 16; r++) {
        int idx = tid + r * 256;         // 0..4095
        int p = idx >> 5, seg = idx & 31;
        int gp = pairbase + p;
        float4 v = make_float4(0.f, 0.f, 0.f, 0.f);
        if (gp < NPAIRS) {
            int atom = ind2[2 * gp + (seg >> 4)];
            v = ((const float4*)g_h)[atom * 16 + (seg & 15)];
        }
        ((float4*)sPIJ)[idx] = v;
    }
    __syncthreads();

    const int pr = tid >> 4, cr = tid & 15;

    // ---- Stage 1: ww1 = tanh(pij @ w1 + b1)  [128x128]@[128x64]
    {
        float acc[8][4];
#pragma unroll
        for (int i = 0; i < 8; i++) { acc[i][0] = acc[i][1] = acc[i][2] = acc[i][3] = 0.f; }
        const float* A = sPIJ + pr * 8 * 128;
        const float* W = sWA + cr * 4;
#pragma unroll 4
        for (int k4 = 0; k4 < 32; k4++) mm8(acc, A, 128, W, 64, k4);
        float4 bv = *(const float4*)(sB1 + cr * 4);
        float* o = sWW1 + pr * 8 * 64 + cr * 4;
#pragma unroll
        for (int i = 0; i < 8; i++) {
            float4 v;
            v.x = tfast(acc[i][0] + bv.x);
            v.y = tfast(acc[i][1] + bv.y);
            v.z = tfast(acc[i][2] + bv.z);
            v.w = tfast(acc[i][3] + bv.w);
            *(float4*)(o + i * 64) = v;
        }
    }
    __syncthreads();

    // Reload sWA with ii weights (w1 dead); completes before next sync
    for (int i = tid; i < 1024; i += 256) ((float4*)sWA)[i] = ((const float4*)wi1)[i];
    for (int i = tid; i < 1024; i += 256) ((float4*)(sWA + 4096))[i] = ((const float4*)wi2)[i];

    // ---- Stage 2: inter[p][c] = sum_b tanh((ww1@w2)[p][c*4+b]+b2) * basis[p][b]
    float* sInter = sPIJ;
    {
        const int c = tid & 63;
        const int pg = tid >> 6;   // 0..3, pairs pg*32..+31
        const float* Wc = sW2 + c * 4;
        const float4 b2v = *(const float4*)(sB2 + c * 4);
#pragma unroll 1
        for (int ch = 0; ch < 4; ch++) {
            const int pb = pg * 32 + ch * 8;
            float acc[8][4];
#pragma unroll
            for (int i = 0; i < 8; i++) { acc[i][0] = acc[i][1] = acc[i][2] = acc[i][3] = 0.f; }
            const float* A = sWW1 + pb * 64;
#pragma unroll 4
            for (int k4 = 0; k4 < 16; k4++) mm8(acc, A, 64, Wc, 256, k4);
#pragma unroll
            for (int i = 0; i < 8; i++) {
                float4 bs = ((const float4*)sBasis)[pb + i];
                float v = tfast(acc[i][0] + b2v.x) * bs.x
                        + tfast(acc[i][1] + b2v.y) * bs.y
                        + tfast(acc[i][2] + b2v.z) * bs.z
                        + tfast(acc[i][3] + b2v.w) * bs.w;
                sInter[(pb + i) * 64 + c] = v;
            }
        }
    }
    __syncthreads();

    // ---- Stage 3: t1 = tanh(inter @ ii_w1)
    float* sT1 = sPIJ + 8192;
    {
        float acc[8][4];
#pragma unroll
        for (int i = 0; i < 8; i++) { acc[i][0] = acc[i][1] = acc[i][2] = acc[i][3] = 0.f; }
        const float* A = sInter + pr * 8 * 64;
        const float* W = sWA + cr * 4;
#pragma unroll 4
        for (int k4 = 0; k4 < 16; k4++) mm8(acc, A, 64, W, 64, k4);
        float* o = sT1 + pr * 8 * 64 + cr * 4;
#pragma unroll
        for (int i = 0; i < 8; i++) {
            float4 v;
            v.x = tfast(acc[i][0]); v.y = tfast(acc[i][1]);
            v.z = tfast(acc[i][2]); v.w = tfast(acc[i][3]);
            *(float4*)(o + i * 64) = v;
        }
    }
    __syncthreads();

    // ---- Stage 4: t2 = tanh(t1 @ ii_w2); atomic scatter into newp[ind_i]
    {
        float acc[8][4];
#pragma unroll
        for (int i = 0; i < 8; i++) { acc[i][0] = acc[i][1] = acc[i][2] = acc[i][3] = 0.f; }
        const float* A = sT1 + pr * 8 * 64;
        const float* W = sWA + 4096 + cr * 4;
#pragma unroll 4
        for (int k4 = 0; k4 < 16; k4++) mm8(acc, A, 64, W, 64, k4);
#pragma unroll
        for (int i = 0; i < 8; i++) {
            int a = sIdx[pr * 8 + i];
            if (a >= 0) {
                float* p = g_newp + a * 64 + cr * 4;
                atomicAdd(p + 0, tfast(acc[i][0]));
                atomicAdd(p + 1, tfast(acc[i][1]));
                atomicAdd(p + 2, tfast(acc[i][2]));
                atomicAdd(p + 3, tfast(acc[i][3]));
            }
        }
    }
}

// ---------------------------------------------------------------------------
// Atom pre-kernel: h = tanh(tanh(p@W1+b1)@W2+b2); also zeroes g_newp.
// 64 atoms per block, 256 threads.
// ---------------------------------------------------------------------------
#define PRE_SMEM_BYTES (12352 * 4)

__global__ __launch_bounds__(256, 1) void atom_pre_kernel(
    const float* __restrict__ prop, int d,
    const float* __restrict__ w1, const float* __restrict__ b1,
    const float* __restrict__ w2, const float* __restrict__ b2)
{
    extern __shared__ float sm[];
    float* sSrc = sm;           // 64*64 (row stride 64)
    float* sW   = sm + 4096;    // 64*64
    float* sH   = sm + 8192;    // 64*64
    float* sB   = sm + 12288;   // 64

    const int tid = threadIdx.x;
    const int abase = blockIdx.x * 64;
    const int K0 = (d == 0) ? 16 : 64;
    const int kq = K0 >> 2;
    const float* src = (d == 0) ? prop : g_p;

    for (int i = tid; i < K0 * 64; i += 256) sW[i] = w1[i];
    if (tid < 64) sB[tid] = b1[tid];
    for (int i = tid; i < 64 * kq; i += 256) {
        int a = i / kq, seg = i % kq;
        float4 v = make_float4(0.f, 0.f, 0.f, 0.f);
        if (abase + a < NATOMS) v = ((const float4*)src)[(abase + a) * kq + seg];
        *(float4*)(sSrc + a * 64 + seg * 4) = v;
    }
    // zero newp for these atoms (consumed by this depth's pair kernel)
    for (int i = tid; i < 1024; i += 256) {
        int a = i >> 4;
        if (abase + a < NATOMS)
            ((float4*)g_newp)[(abase + a) * 16 + (i & 15)] = make_float4(0.f, 0.f, 0.f, 0.f);
    }
    __syncthreads();

    const int ar = tid >> 4, cr = tid & 15;
    {
        float acc[4][4];
#pragma unroll
        for (int i = 0; i < 4; i++) { acc[i][0] = acc[i][1] = acc[i][2] = acc[i][3] = 0.f; }
        const float* A = sSrc + ar * 4 * 64;
        const float* W = sW + cr * 4;
        for (int k4 = 0; k4 < kq; k4++) mm4(acc, A, 64, W, 64, k4);
        float4 bv = *(const float4*)(sB + cr * 4);
#pragma unroll
        for (int i = 0; i < 4; i++) {
            float4 v;
            v.x = tfast(acc[i][0] + bv.x); v.y = tfast(acc[i][1] + bv.y);
            v.z = tfast(acc[i][2] + bv.z); v.w = tfast(acc[i][3] + bv.w);
            *(float4*)(sH + (ar * 4 + i) * 64 + cr * 4) = v;
        }
    }
    __syncthreads();
    for (int i = tid; i < 4096; i += 256) sW[i] = w2[i];
    if (tid < 64) sB[tid] = b2[tid];
    __syncthreads();
    {
        float acc[4][4];
#pragma unroll
        for (int i = 0; i < 4; i++) { acc[i][0] = acc[i][1] = acc[i][2] = acc[i][3] = 0.f; }
        const float* A = sH + ar * 4 * 64;
        const float* W = sW + cr * 4;
#pragma unroll 4
        for (int k4 = 0; k4 < 16; k4++) mm4(acc, A, 64, W, 64, k4);
        float4 bv = *(const float4*)(sB + cr * 4);
#pragma unroll
        for (int i = 0; i < 4; i++) {
            int a = abase + ar * 4 + i;
            if (a < NATOMS) {
                float4 v;
                v.x = tfast(acc[i][0] + bv.x); v.y = tfast(acc[i][1] + bv.y);
                v.z = tfast(acc[i][2] + bv.z); v.w = tfast(acc[i][3] + bv.w);
                ((float4*)g_h)[a * 16 + cr] = v;
            }
        }
    }
}

// ---------------------------------------------------------------------------
// Atom post-kernel: p update + output head accumulation.
// ---------------------------------------------------------------------------
#define POST_SMEM_BYTES (12928 * 4)

__global__ __launch_bounds__(256, 1) void atom_post_kernel(
    const float* __restrict__ prop, const float* __restrict__ res0w,
    const float* __restrict__ w1, const float* __restrict__ b1,
    const float* __restrict__ w2, const float* __restrict__ b2,
    const float* __restrict__ wo, float* __restrict__ out, int d)
{
    extern __shared__ float sm[];
    float* bufA = sm;            // 64*68 (padded stride 68)
    float* bufB = sm + 4352;     // 64*68
    float* sW   = sm + 8704;     // 4096
    float* sB   = sm + 12800;    // 64
    float* sWo  = sm + 12864;    // 64

    const int tid = threadIdx.x;
    const int abase = blockIdx.x * 64;
    const int ar = tid >> 4, cr = tid & 15;

    float pn[4][4];
#pragma unroll
    for (int i = 0; i < 4; i++) { pn[i][0] = pn[i][1] = pn[i][2] = pn[i][3] = 0.f; }

    if (d == 0) {
        // pn = prop @ res0_w   (K = 16)
        for (int i = tid; i < 1024; i += 256) sW[i] = res0w[i];
        for (int i = tid; i < 256; i += 256) {
            int a = i >> 2, seg = i & 3;
            float4 v = make_float4(0.f, 0.f, 0.f, 0.f);
            if (abase + a < NATOMS) v = ((const float4*)prop)[(abase + a) * 4 + seg];
            *(float4*)(bufB + a * 16 + seg * 4) = v;  // stride 16 (temporary layout)
        }
        __syncthreads();
        const float* A = bufB + ar * 4 * 16;
        const float* W = sW + cr * 4;
#pragma unroll
        for (int k4 = 0; k4 < 4; k4++) mm4(pn, A, 16, W, 64, k4);
    }

    // pnew = (d==0 ? prop@res0 : p) + newp ; write to g_p and bufA
#pragma unroll
    for (int i = 0; i < 4; i++) {
        int a = abase + ar * 4 + i;
        float4 v = make_float4(0.f, 0.f, 0.f, 0.f);
        if (a < NATOMS) {
            float4 np = ((const float4*)g_newp)[a * 16 + cr];
            if (d == 0) {
                v.x = pn[i][0] + np.x; v.y = pn[i][1] + np.y;
                v.z = pn[i][2] + np.z; v.w = pn[i][3] + np.w;
            } else {
                float4 pv = ((const float4*)g_p)[a * 16 + cr];
                v.x = pv.x + np.x; v.y = pv.y + np.y;
                v.z = pv.z + np.z; v.w = pv.w + np.w;
            }
            ((float4*)g_p)[a * 16 + cr] = v;
        }
        *(float4*)(bufA + (ar * 4 + i) * 68 + cr * 4) = v;
    }
    __syncthreads();

    for (int i = tid; i < 4096; i += 256) sW[i] = w1[i];
    if (tid < 64) { sB[tid] = b1[tid]; sWo[tid] = wo[tid]; }
    __syncthreads();

    // o1 = tanh(pnew @ out_w1 + b1) -> bufB (stride 68)
    {
        float acc[4][4];
#pragma unroll
        for (int i = 0; i < 4; i++) { acc[i][0] = acc[i][1] = acc[i][2] = acc[i][3] = 0.f; }
        const float* A = bufA + ar * 4 * 68;
        const float* W = sW + cr * 4;
#pragma unroll 4
        for (int k4 = 0; k4 < 16; k4++) mm4(acc, A, 68, W, 64, k4);
        float4 bv = *(const float4*)(sB + cr * 4);
#pragma unroll
        for (int i = 0; i < 4; i++) {
            float4 v;
            v.x = tfast(acc[i][0] + bv.x); v.y = tfast(acc[i][1] + bv.y);
            v.z = tfast(acc[i][2] + bv.z); v.w = tfast(acc[i][3] + bv.w);
            *(float4*)(bufB + (ar * 4 + i) * 68 + cr * 4) = v;
        }
    }
    __syncthreads();
    for (int i = tid; i < 4096; i += 256) sW[i] = w2[i];
    if (tid < 64) sB[tid] = b2[tid];
    __syncthreads();

    // o2 = tanh(o1 @ out_w2 + b2) -> bufA
    {
        float acc[4][4];
#pragma unroll
        for (int i = 0; i < 4; i++) { acc[i][0] = acc[i][1] = acc[i][2] = acc[i][3] = 0.f; }
        const float* A = bufB + ar * 4 * 68;
        const float* W = sW + cr * 4;
#pragma unroll 4
        for (int k4 = 0; k4 < 16; k4++) mm4(acc, A, 68, W, 64, k4);
        float4 bv = *(const float4*)(sB + cr * 4);
#pragma unroll
        for (int i = 0; i < 4; i++) {
            float4 v;
            v.x = tfast(acc[i][0] + bv.x); v.y = tfast(acc[i][1] + bv.y);
            v.z = tfast(acc[i][2] + bv.z); v.w = tfast(acc[i][3] + bv.w);
            *(float4*)(bufA + (ar * 4 + i) * 68 + cr * 4) = v;
        }
    }
    __syncthreads();

    // output += o2 @ out_wo  (one thread per atom; stride-68 rows avoid conflicts)
    if (tid < 64) {
        int a = abase + tid;
        if (a < NATOMS) {
            float s = 0.f;
            const float* row = bufA + tid * 68;
#pragma unroll 8
            for (int c = 0; c < 64; c++) s = fmaf(row[c], sWo[c], s);
            out[a] = (d == 0) ? s : (out[a] + s);
        }
    }
}

// ---------------------------------------------------------------------------
extern "C" void kernel_launch(void* const* d_in, const int* in_sizes, int n_in,
                              void* d_out, int out_size) {
    const int*   ind2   = (const int*)d_in[0];
    const float* prop   = (const float*)d_in[1];
    const float* basis  = (const float*)d_in[2];
    const float* pp0_w1 = (const float*)d_in[3];
    const float* pp0_b1 = (const float*)d_in[4];
    const float* pp_w1  = (const float*)d_in[5];
    const float* pp_b1  = (const float*)d_in[6];
    const float* pp_w2  = (const float*)d_in[7];
    const float* pp_b2  = (const float*)d_in[8];
    const float* pi_w1  = (const float*)d_in[9];
    const float* pi_b1  = (const float*)d_in[10];
    const float* pi_w2  = (const float*)d_in[11];
    const float* pi_b2  = (const float*)d_in[12];
    const float* ii_w1  = (const float*)d_in[13];
    const float* ii_w2  = (const float*)d_in[14];
    const float* res0   = (const float*)d_in[15];
    const float* ow1    = (const float*)d_in[16];
    const float* ob1    = (const float*)d_in[17];
    const float* ow2    = (const float*)d_in[18];
    const float* ob2    = (const float*)d_in[19];
    const float* owo    = (const float*)d_in[20];
    float* out = (float*)d_out;

    static bool inited = false;
    if (!inited) {
        cudaFuncSetAttribute(pair_kernel, cudaFuncAttributeMaxDynamicSharedMemorySize, PAIR_SMEM_BYTES);
        cudaFuncSetAttribute(atom_pre_kernel, cudaFuncAttributeMaxDynamicSharedMemorySize, PRE_SMEM_BYTES);
        cudaFuncSetAttribute(atom_post_kernel, cudaFuncAttributeMaxDynamicSharedMemorySize, POST_SMEM_BYTES);
        inited = true;
    }

    const int atom_blocks = (NATOMS + 63) / 64;     // 391
    const int pair_blocks = (NPAIRS + 127) / 128;   // 3907

    for (int d = 0; d < 4; d++) {
        const float* w1 = (d == 0) ? pp0_w1 : pp_w1 + (d - 1) * 4096;
        const float* b1 = (d == 0) ? pp0_b1 : pp_b1 + (d - 1) * 64;
        atom_pre_kernel<<<atom_blocks, 256, PRE_SMEM_BYTES>>>(
            prop, d, w1, b1, pp_w2 + d * 4096, pp_b2 + d * 64);
        pair_kernel<<<pair_blocks, 256, PAIR_SMEM_BYTES>>>(
            ind2, basis,
            pi_w1 + d * 8192, pi_b1 + d * 64,
            pi_w2 + d * 16384, pi_b2 + d * 256,
            ii_w1 + d * 4096, ii_w2 + d * 4096);
        atom_post_kernel<<<atom_blocks, 256, POST_SMEM_BYTES>>>(
            prop, res0,
            ow1 + d * 4096, ob1 + d * 64,
            ow2 + d * 4096, ob2 + d * 64,
            owo + d * 64, out, d);
    }
}